// round 2
// baseline (speedup 1.0000x reference)
#include <cuda_runtime.h>

// ---- folded-parameter layout in shared P[256] ----
// [0..32)   G   gate weights [i*8+e]
// [32..40)  gb  gate bias
// [40..200) E   per-expert 20 floats: [e*20 + i*4 + j]=EP(4x4), [e*20+16+j]=epb
// [200..216) RP  resid (folded thru proj)  [i*4+j]
// [216..220) rpb
// [220..224) dC  differenced combine weights (col1-col0, folded thru w_embed)
// [224]      dcb differenced combine bias
// [225..229) pb  proj bias

__device__ double       d_acc[16];   // [0..8) sum gate probs, [8..16) argmax counts
__device__ unsigned int d_count = 0;

__global__ __launch_bounds__(256) void moe_fused_kernel(
    const float4* __restrict__ x4,
    const float* __restrict__ w_embed,  const float* __restrict__ b_embed,
    const float* __restrict__ gate_w,   const float* __restrict__ expert_w,
    const float* __restrict__ expert_b, const float* __restrict__ resid_w,
    const float* __restrict__ resid_b,  const float* __restrict__ comb_w,
    const float* __restrict__ comb_b,   const float* __restrict__ proj_w,
    const float* __restrict__ proj_b,
    float4* __restrict__ o4, float* __restrict__ out, int n, int out_size)
{
    __shared__ float P[256];
    __shared__ float sT[512];     // (w_embed @ expert_w[e])[i][k]
    __shared__ float sTb[128];    // (b_embed @ expert_w[e])[k]
    __shared__ float sR[64];      // (w_embed @ resid_w)[i][k]
    __shared__ float sRb[16];     // (b_embed @ resid_w)[k] + resid_b
    __shared__ float red[8][16];
    __shared__ unsigned s_last;

    const int t = threadIdx.x;

    // ================= per-block parameter fold (tiny, L2-resident) =================
    // phase A: sT, 2 entries per thread
    {
        int i0 = t, i1 = t + 256;
        int e0 = i0 >> 6, r0 = (i0 >> 4) & 3, k0 = i0 & 15;
        int e1 = i1 >> 6, r1 = (i1 >> 4) & 3, k1 = i1 & 15;
        float a0 = 0.f, a1 = 0.f;
        #pragma unroll
        for (int m = 0; m < 16; m++) {
            a0 = fmaf(w_embed[r0 * 16 + m], expert_w[(e0 * 16 + m) * 16 + k0], a0);
            a1 = fmaf(w_embed[r1 * 16 + m], expert_w[(e1 * 16 + m) * 16 + k1], a1);
        }
        sT[i0] = a0; sT[i1] = a1;
    }
    // phase B: independent small folds
    if (t < 128) {                        // sTb
        int e = t >> 4, k = t & 15;
        float acc = 0.f;
        #pragma unroll
        for (int m = 0; m < 16; m++)
            acc = fmaf(b_embed[m], expert_w[(e * 16 + m) * 16 + k], acc);
        sTb[t] = acc;
    } else if (t < 192) {                 // sR
        int u = t - 128, i = u >> 4, k = u & 15;
        float acc = 0.f;
        #pragma unroll
        for (int m = 0; m < 16; m++)
            acc = fmaf(w_embed[i * 16 + m], resid_w[m * 16 + k], acc);
        sR[u] = acc;
    } else if (t < 208) {                 // sRb
        int k = t - 192;
        float acc = resid_b[k];
        #pragma unroll
        for (int m = 0; m < 16; m++)
            acc = fmaf(b_embed[m], resid_w[m * 16 + k], acc);
        sRb[k] = acc;
    } else if (t < 240) {                 // G
        int u = t - 208, i = u >> 3, e = u & 7;
        float acc = 0.f;
        #pragma unroll
        for (int m = 0; m < 16; m++)
            acc = fmaf(w_embed[i * 16 + m], gate_w[m * 8 + e], acc);
        P[i * 8 + e] = acc;
    } else {                              // gb
        int e = t - 240;
        float acc = 0.f;
        #pragma unroll
        for (int m = 0; m < 16; m++)
            acc = fmaf(b_embed[m], gate_w[m * 8 + e], acc);
        P[32 + e] = acc;
    }
    __syncthreads();

    // phase C: multiply staged folds by proj_w + misc
    if (t < 128) {                        // EP
        int e = t >> 4, i = (t >> 2) & 3, j = t & 3;
        float acc = 0.f;
        #pragma unroll
        for (int k = 0; k < 16; k++)
            acc = fmaf(sT[(e * 4 + i) * 16 + k], proj_w[k * 4 + j], acc);
        P[40 + e * 20 + i * 4 + j] = acc;
    } else if (t < 160) {                 // epb
        int u = t - 128, e = u >> 2, j = u & 3;
        float acc = 0.f;
        #pragma unroll
        for (int k = 0; k < 16; k++)
            acc = fmaf(sTb[e * 16 + k] + expert_b[e * 16 + k], proj_w[k * 4 + j], acc);
        P[40 + e * 20 + 16 + j] = acc;
    } else if (t < 176) {                 // RP
        int u = t - 160, i = u >> 2, j = u & 3;
        float acc = 0.f;
        #pragma unroll
        for (int k = 0; k < 16; k++)
            acc = fmaf(sR[i * 16 + k], proj_w[k * 4 + j], acc);
        P[200 + i * 4 + j] = acc;
    } else if (t < 180) {                 // rpb
        int j = t - 176;
        float acc = 0.f;
        #pragma unroll
        for (int k = 0; k < 16; k++)
            acc = fmaf(sRb[k], proj_w[k * 4 + j], acc);
        P[216 + j] = acc;
    } else if (t < 184) {                 // dC (combine col1-col0 folded thru w_embed)
        int i = t - 180;
        float acc = 0.f;
        #pragma unroll
        for (int m = 0; m < 16; m++)
            acc = fmaf(w_embed[i * 16 + m], comb_w[m * 2 + 1] - comb_w[m * 2], acc);
        P[220 + i] = acc;
    } else if (t == 184) {                // dcb
        float acc = comb_b[1] - comb_b[0];
        #pragma unroll
        for (int m = 0; m < 16; m++)
            acc = fmaf(b_embed[m], comb_w[m * 2 + 1] - comb_w[m * 2], acc);
        P[224] = acc;
    } else if (t < 189) {                 // pb
        P[225 + (t - 185)] = proj_b[t - 185];
    }
    __syncthreads();

    // ================= hoist loop-invariant params into registers =================
    float Gx[8], Gy[8], Gz[8], Gw[8], Gb[8];
    #pragma unroll
    for (int e = 0; e < 8; e++) {
        Gx[e] = P[e];      Gy[e] = P[8 + e];  Gz[e] = P[16 + e];
        Gw[e] = P[24 + e]; Gb[e] = P[32 + e];
    }
    float Rp[16], Rb[4], Dc[4], Pb[4];
    #pragma unroll
    for (int k = 0; k < 16; k++) Rp[k] = P[200 + k];
    #pragma unroll
    for (int j = 0; j < 4; j++) { Rb[j] = P[216 + j]; Dc[j] = P[220 + j]; Pb[j] = P[225 + j]; }
    const float Dcb = P[224];

    // ================= main streaming loop =================
    float S[8] = {0.f, 0.f, 0.f, 0.f, 0.f, 0.f, 0.f, 0.f};
    unsigned cnt = 0;      // 8 nibble counters (<= 4 tokens/thread)

    const int stride = blockDim.x * gridDim.x;
    #pragma unroll 2
    for (int i = blockIdx.x * blockDim.x + t; i < n; i += stride) {
        const float4 xv = x4[i];

        // gate logits (register coefficients)
        float lg[8];
        #pragma unroll
        for (int e = 0; e < 8; e++)
            lg[e] = fmaf(xv.w, Gw[e], fmaf(xv.z, Gz[e],
                    fmaf(xv.y, Gy[e], fmaf(xv.x, Gx[e], Gb[e]))));

        // first-max argmax (matches jnp.argmax)
        float m = lg[0]; int idx = 0;
        #pragma unroll
        for (int e = 1; e < 8; e++)
            if (lg[e] > m) { m = lg[e]; idx = e; }

        // softmax probs + per-expert prob sums
        float p[8], sum = 0.f;
        #pragma unroll
        for (int e = 0; e < 8; e++) { p[e] = __expf(lg[e] - m); sum += p[e]; }
        const float inv = __fdividef(1.f, sum);   // == gates[idx]
        #pragma unroll
        for (int e = 0; e < 8; e++) S[e] = fmaf(p[e], inv, S[e]);
        cnt += 1u << (idx << 2);

        // combine weights: softmax over 2 == sigmoid of differenced linear form
        const float dl = fmaf(xv.w, Dc[3], fmaf(xv.z, Dc[2],
                         fmaf(xv.y, Dc[1], fmaf(xv.x, Dc[0], Dcb))));
        const float ex  = __expf(dl);
        const float cw0 = __fdividef(1.f, 1.f + ex);
        const float cw1 = 1.f - cw0;
        const float a   = cw0 * inv;

        // expert (shared, stride-20 conflict-free) + resid (registers), both pre-folded thru proj
        const float* Ep = &P[40 + idx * 20];
        float ov[4];
        #pragma unroll
        for (int j = 0; j < 4; j++) {
            float ev = fmaf(xv.w, Ep[12 + j], fmaf(xv.z, Ep[8 + j],
                       fmaf(xv.y, Ep[ 4 + j], fmaf(xv.x, Ep[j], Ep[16 + j]))));
            float rv = fmaf(xv.w, Rp[12 + j], fmaf(xv.z, Rp[8 + j],
                       fmaf(xv.y, Rp[ 4 + j], fmaf(xv.x, Rp[j], Rb[j]))));
            ov[j] = fmaf(a, ev, fmaf(cw1, rv, Pb[j]));
        }
        float4 o; o.x = ov[0]; o.y = ov[1]; o.z = ov[2]; o.w = ov[3];
        o4[i] = o;
    }

    // ================= aux reduction: warp -> block -> global =================
    float Cf[8];
    #pragma unroll
    for (int e = 0; e < 8; e++) Cf[e] = (float)((cnt >> (e << 2)) & 0xFu);

    #pragma unroll
    for (int e = 0; e < 8; e++) {
        #pragma unroll
        for (int off = 16; off; off >>= 1) {
            S[e]  += __shfl_down_sync(0xffffffffu, S[e],  off);
            Cf[e] += __shfl_down_sync(0xffffffffu, Cf[e], off);
        }
    }
    const int lane = t & 31, w = t >> 5;
    if (lane == 0) {
        #pragma unroll
        for (int e = 0; e < 8; e++) { red[w][e] = S[e]; red[w][8 + e] = Cf[e]; }
    }
    __syncthreads();
    if (t < 16) {
        float v = 0.f;
        #pragma unroll
        for (int w2 = 0; w2 < 8; w2++) v += red[w2][t];
        atomicAdd(&d_acc[t], (double)v);
        __threadfence();   // make this thread's d_acc update device-visible
    }
    __syncthreads();

    // ================= last-block finalize (replay-safe reset) =================
    if (t == 0) {
        unsigned old = atomicAdd(&d_count, 1u);
        s_last = (old == gridDim.x - 1) ? 1u : 0u;
    }
    __syncthreads();
    if (s_last && t == 0) {
        volatile double* acc = d_acc;   // bypass L1; L2 is point of coherence
        double s = 0.0;
        #pragma unroll
        for (int e = 0; e < 8; e++) s += acc[e] * acc[8 + e];
        if (out_size > n * 4) {
            const double dn = (double)n;
            out[n * 4] = (float)(8.0 * s / (dn * dn));
        }
        #pragma unroll
        for (int k = 0; k < 16; k++) acc[k] = 0.0;   // reset for next graph replay
        __threadfence();
        d_count = 0;
    }
}

extern "C" void kernel_launch(void* const* d_in, const int* in_sizes, int n_in,
                              void* d_out, int out_size)
{
    const float* x        = (const float*)d_in[0];
    const float* w_embed  = (const float*)d_in[1];
    const float* b_embed  = (const float*)d_in[2];
    const float* gate_w   = (const float*)d_in[3];
    const float* expert_w = (const float*)d_in[4];
    const float* expert_b = (const float*)d_in[5];
    const float* resid_w  = (const float*)d_in[6];
    const float* resid_b  = (const float*)d_in[7];
    const float* comb_w   = (const float*)d_in[8];
    const float* comb_b   = (const float*)d_in[9];
    const float* proj_w   = (const float*)d_in[10];
    const float* proj_b   = (const float*)d_in[11];

    const int n = in_sizes[0] / 4;          // tokens

    // TPT = 4 tokens/thread -> nibble counters safe; fine tail granularity
    int grid = (n + 256 * 4 - 1) / (256 * 4);
    if (grid < 1) grid = 1;

    moe_fused_kernel<<<grid, 256>>>(
        (const float4*)x, w_embed, b_embed, gate_w, expert_w, expert_b,
        resid_w, resid_b, comb_w, comb_b, proj_w, proj_b,
        (float4*)d_out, (float*)d_out, n, out_size);
}

// round 3
// speedup vs baseline: 1.2316x; 1.2316x over previous
#include <cuda_runtime.h>

typedef unsigned long long ull;

// ---- packed f32x2 helpers (ptxas never auto-fuses these) ----
__device__ __forceinline__ ull fma2(ull a, ull b, ull c) {
    ull d; asm("fma.rn.f32x2 %0,%1,%2,%3;" : "=l"(d) : "l"(a), "l"(b), "l"(c)); return d;
}
__device__ __forceinline__ ull pk2(float lo, float hi) {
    ull d; asm("mov.b64 %0,{%1,%2};" : "=l"(d) : "f"(lo), "f"(hi)); return d;
}
__device__ __forceinline__ float2 upk2(ull v) {
    float2 r; asm("mov.b64 {%0,%1},%2;" : "=f"(r.x), "=f"(r.y) : "l"(v)); return r;
}
__device__ __forceinline__ float ex2(float x) {
    float r; asm("ex2.approx.ftz.f32 %0,%1;" : "=f"(r) : "f"(x)); return r;
}

#define LOG2E 1.4426950408889634f

__device__ double       d_acc[16];   // [0..8) sum gate probs, [8..16) argmax counts
__device__ unsigned int d_count = 0;

__global__ __launch_bounds__(256, 3) void moe_fused_kernel(
    const float4* __restrict__ x4,
    const float* __restrict__ w_embed,  const float* __restrict__ b_embed,
    const float* __restrict__ gate_w,   const float* __restrict__ expert_w,
    const float* __restrict__ expert_b, const float* __restrict__ resid_w,
    const float* __restrict__ resid_b,  const float* __restrict__ comb_w,
    const float* __restrict__ comb_b,   const float* __restrict__ proj_w,
    const float* __restrict__ proj_b,
    float4* __restrict__ o4, float* __restrict__ out, int n, int out_size)
{
    // folded params (pair/float4-friendly layouts, all 16B aligned)
    __shared__ alignas(16) float sGate[40];    // [i*8+e] i<4 rows, [32+e] bias; *LOG2E
    __shared__ alignas(16) float sExp[160];    // [e*20 + i*4 + j], bias [e*20+16+j]
    __shared__ alignas(16) float sResid[20];   // [i*4+j], bias [16+j]
    __shared__ alignas(16) float sComb[8];     // dC[0..4)=*LOG2E, dcb at [4]
    __shared__ alignas(16) float sPb[4];
    // fold staging
    __shared__ float sT[512];
    __shared__ float sTb[128];
    __shared__ float sR[64];
    __shared__ float sRb[16];
    __shared__ float red[8][16];
    __shared__ unsigned s_last;

    const int t = threadIdx.x;

    // ================= per-block parameter fold (L2-resident, one-time) =================
    // phase A: sT[e][i][k] = (w_embed @ expert_w[e])[i][k], 2 per thread
    {
        int i0 = t, i1 = t + 256;
        int e0 = i0 >> 6, r0 = (i0 >> 4) & 3, k0 = i0 & 15;
        int e1 = i1 >> 6, r1 = (i1 >> 4) & 3, k1 = i1 & 15;
        float a0 = 0.f, a1 = 0.f;
        #pragma unroll
        for (int m = 0; m < 16; m++) {
            a0 = fmaf(w_embed[r0 * 16 + m], expert_w[(e0 * 16 + m) * 16 + k0], a0);
            a1 = fmaf(w_embed[r1 * 16 + m], expert_w[(e1 * 16 + m) * 16 + k1], a1);
        }
        sT[i0] = a0; sT[i1] = a1;
    }
    // phase B
    if (t < 128) {                        // sTb = b_embed @ expert_w[e]
        int e = t >> 4, k = t & 15;
        float acc = 0.f;
        #pragma unroll
        for (int m = 0; m < 16; m++)
            acc = fmaf(b_embed[m], expert_w[(e * 16 + m) * 16 + k], acc);
        sTb[t] = acc;
    } else if (t < 192) {                 // sR = w_embed @ resid_w
        int u = t - 128, i = u >> 4, k = u & 15;
        float acc = 0.f;
        #pragma unroll
        for (int m = 0; m < 16; m++)
            acc = fmaf(w_embed[i * 16 + m], resid_w[m * 16 + k], acc);
        sR[u] = acc;
    } else if (t < 208) {                 // sRb = b_embed @ resid_w + resid_b
        int k = t - 192;
        float acc = resid_b[k];
        #pragma unroll
        for (int m = 0; m < 16; m++)
            acc = fmaf(b_embed[m], resid_w[m * 16 + k], acc);
        sRb[k] = acc;
    } else if (t < 240) {                 // gate weights (log2e-scaled)
        int u = t - 208, i = u >> 3, e = u & 7;
        float acc = 0.f;
        #pragma unroll
        for (int m = 0; m < 16; m++)
            acc = fmaf(w_embed[i * 16 + m], gate_w[m * 8 + e], acc);
        sGate[i * 8 + e] = acc * LOG2E;
    } else if (t < 248) {                 // gate bias (log2e-scaled)
        int e = t - 240;
        float acc = 0.f;
        #pragma unroll
        for (int m = 0; m < 16; m++)
            acc = fmaf(b_embed[m], gate_w[m * 8 + e], acc);
        sGate[32 + e] = acc * LOG2E;
    } else if (t < 252) {                 // differenced combine weights (log2e-scaled)
        int i = t - 248;
        float acc = 0.f;
        #pragma unroll
        for (int m = 0; m < 16; m++)
            acc = fmaf(w_embed[i * 16 + m], comb_w[m * 2 + 1] - comb_w[m * 2], acc);
        sComb[i] = acc * LOG2E;
    } else if (t == 252) {                // differenced combine bias
        float acc = comb_b[1] - comb_b[0];
        #pragma unroll
        for (int m = 0; m < 16; m++)
            acc = fmaf(b_embed[m], comb_w[m * 2 + 1] - comb_w[m * 2], acc);
        sComb[4] = acc * LOG2E;
    }
    __syncthreads();

    // phase C: multiply staged folds by proj_w
    if (t < 128) {                        // EP[e][i][j]
        int e = t >> 4, i = (t >> 2) & 3, j = t & 3;
        float acc = 0.f;
        #pragma unroll
        for (int k = 0; k < 16; k++)
            acc = fmaf(sT[(e * 4 + i) * 16 + k], proj_w[k * 4 + j], acc);
        sExp[e * 20 + i * 4 + j] = acc;
    } else if (t < 160) {                 // epb[e][j]
        int u = t - 128, e = u >> 2, j = u & 3;
        float acc = 0.f;
        #pragma unroll
        for (int k = 0; k < 16; k++)
            acc = fmaf(sTb[e * 16 + k] + expert_b[e * 16 + k], proj_w[k * 4 + j], acc);
        sExp[e * 20 + 16 + j] = acc;
    } else if (t < 176) {                 // RP[i][j]
        int u = t - 160, i = u >> 2, j = u & 3;
        float acc = 0.f;
        #pragma unroll
        for (int k = 0; k < 16; k++)
            acc = fmaf(sR[i * 16 + k], proj_w[k * 4 + j], acc);
        sResid[i * 4 + j] = acc;
    } else if (t < 180) {                 // rpb[j]
        int j = t - 176;
        float acc = 0.f;
        #pragma unroll
        for (int k = 0; k < 16; k++)
            acc = fmaf(sRb[k], proj_w[k * 4 + j], acc);
        sResid[16 + j] = acc;
    } else if (t < 184) {                 // proj bias
        sPb[t - 180] = proj_b[t - 180];
    }
    __syncthreads();

    // pair-typed views of shared params
    const ull* Gp = (const ull*)sGate;                 // [i*4+k] rows, [16+k] bias
    const ull* Rp = (const ull*)sResid;                // rows [i*2], [i*2+1]; bias [8],[9]
    const ull  Pbp0 = ((const ull*)sPb)[0];
    const ull  Pbp1 = ((const ull*)sPb)[1];
    const float Dc0 = sComb[0], Dc1 = sComb[1], Dc2 = sComb[2], Dc3 = sComb[3];
    const float Dcb = sComb[4];

    // ================= main streaming loop =================
    float S[8] = {0.f, 0.f, 0.f, 0.f, 0.f, 0.f, 0.f, 0.f};
    unsigned cnt = 0;      // 8 nibble counters (tokens/thread <= 15)

    const int stride = blockDim.x * gridDim.x;
    for (int i = blockIdx.x * blockDim.x + t; i < n; i += stride) {
        const float4 xv = x4[i];
        const ull xx = pk2(xv.x, xv.x), yy = pk2(xv.y, xv.y);
        const ull zz = pk2(xv.z, xv.z), ww = pk2(xv.w, xv.w);

        // gate logits in log2 domain (4 packed pairs)
        float lg[8];
        #pragma unroll
        for (int k = 0; k < 4; k++) {
            ull v = fma2(xx, Gp[k],      Gp[16 + k]);
            v     = fma2(yy, Gp[4 + k],  v);
            v     = fma2(zz, Gp[8 + k],  v);
            v     = fma2(ww, Gp[12 + k], v);
            float2 f = upk2(v); lg[2 * k] = f.x; lg[2 * k + 1] = f.y;
        }

        // first-max argmax (matches jnp.argmax; log2e scale preserves order)
        float m = lg[0]; int idx = 0;
        #pragma unroll
        for (int e = 1; e < 8; e++)
            if (lg[e] > m) { m = lg[e]; idx = e; }

        // softmax probs via ex2 (exactly exp(lg-m) since coeffs pre-scaled)
        float p[8], sum = 0.f;
        #pragma unroll
        for (int e = 0; e < 8; e++) { p[e] = ex2(lg[e] - m); sum += p[e]; }
        const float inv = __fdividef(1.f, sum);   // == gates[idx] (ex2(0)=1)
        #pragma unroll
        for (int e = 0; e < 8; e++) S[e] = fmaf(p[e], inv, S[e]);
        cnt += 1u << (idx << 2);

        // 2-way combine softmax == sigmoid of differenced linear form (log2 domain)
        const float dl = fmaf(xv.w, Dc3, fmaf(xv.z, Dc2,
                         fmaf(xv.y, Dc1, fmaf(xv.x, Dc0, Dcb))));
        const float cw0 = __fdividef(1.f, 1.f + ex2(dl));
        const float cw1 = 1.f - cw0;
        const float a   = cw0 * inv;

        // expert block: 5x LDS.128 (16B-aligned, stride 80B), packed math
        const ulonglong2* Ep = (const ulonglong2*)(sExp + idx * 20);
        const ulonglong2 e0 = Ep[0], e1 = Ep[1], e2 = Ep[2], e3 = Ep[3], e4 = Ep[4];
        ull v01 = fma2(xx, e0.x, e4.x);
        v01 = fma2(yy, e1.x, v01); v01 = fma2(zz, e2.x, v01); v01 = fma2(ww, e3.x, v01);
        ull v23 = fma2(xx, e0.y, e4.y);
        v23 = fma2(yy, e1.y, v23); v23 = fma2(zz, e2.y, v23); v23 = fma2(ww, e3.y, v23);

        // residual (pre-folded thru proj), packed
        ull r01 = fma2(xx, Rp[0], Rp[8]);
        r01 = fma2(yy, Rp[2], r01); r01 = fma2(zz, Rp[4], r01); r01 = fma2(ww, Rp[6], r01);
        ull r23 = fma2(xx, Rp[1], Rp[9]);
        r23 = fma2(yy, Rp[3], r23); r23 = fma2(zz, Rp[5], r23); r23 = fma2(ww, Rp[7], r23);

        const ull aa = pk2(a, a), cc = pk2(cw1, cw1);
        union { ull u[2]; float4 v; } ou;
        ou.u[0] = fma2(aa, v01, fma2(cc, r01, Pbp0));
        ou.u[1] = fma2(aa, v23, fma2(cc, r23, Pbp1));
        o4[i] = ou.v;
    }

    // ================= aux reduction: warp -> block -> global =================
    float Cf[8];
    #pragma unroll
    for (int e = 0; e < 8; e++) Cf[e] = (float)((cnt >> (e << 2)) & 0xFu);

    #pragma unroll
    for (int e = 0; e < 8; e++) {
        #pragma unroll
        for (int off = 16; off; off >>= 1) {
            S[e]  += __shfl_down_sync(0xffffffffu, S[e],  off);
            Cf[e] += __shfl_down_sync(0xffffffffu, Cf[e], off);
        }
    }
    const int lane = t & 31, w = t >> 5;
    if (lane == 0) {
        #pragma unroll
        for (int e = 0; e < 8; e++) { red[w][e] = S[e]; red[w][8 + e] = Cf[e]; }
    }
    __syncthreads();
    if (t < 16) {
        float v = 0.f;
        #pragma unroll
        for (int w2 = 0; w2 < 8; w2++) v += red[w2][t];
        atomicAdd(&d_acc[t], (double)v);
        __threadfence();
    }
    __syncthreads();

    // ================= last-block finalize (graph-replay-safe reset) =================
    if (t == 0) {
        unsigned old = atomicAdd(&d_count, 1u);
        s_last = (old == gridDim.x - 1) ? 1u : 0u;
    }
    __syncthreads();
    if (s_last && t == 0) {
        volatile double* acc = d_acc;
        double s = 0.0;
        #pragma unroll
        for (int e = 0; e < 8; e++) s += acc[e] * acc[8 + e];
        if (out_size > n * 4) {
            const double dn = (double)n;
            out[n * 4] = (float)(8.0 * s / (dn * dn));
        }
        #pragma unroll
        for (int k = 0; k < 16; k++) acc[k] = 0.0;
        __threadfence();
        d_count = 0;
    }
}

extern "C" void kernel_launch(void* const* d_in, const int* in_sizes, int n_in,
                              void* d_out, int out_size)
{
    const float* x        = (const float*)d_in[0];
    const float* w_embed  = (const float*)d_in[1];
    const float* b_embed  = (const float*)d_in[2];
    const float* gate_w   = (const float*)d_in[3];
    const float* expert_w = (const float*)d_in[4];
    const float* expert_b = (const float*)d_in[5];
    const float* resid_w  = (const float*)d_in[6];
    const float* resid_b  = (const float*)d_in[7];
    const float* comb_w   = (const float*)d_in[8];
    const float* comb_b   = (const float*)d_in[9];
    const float* proj_w   = (const float*)d_in[10];
    const float* proj_b   = (const float*)d_in[11];

    const int n = in_sizes[0] / 4;          // tokens

    // single wave: 3 blocks/SM x 148 SMs; tokens/thread <= 15 keeps nibbles safe
    int grid = 3 * 148;
    int min_grid = (n + 256 * 15 - 1) / (256 * 15);   // never exceed 15 tokens/thread
    if (min_grid > grid) grid = min_grid;
    int max_grid = (n + 255) / 256;                    // no empty blocks
    if (grid > max_grid) grid = max_grid;
    if (grid < 1) grid = 1;

    moe_fused_kernel<<<grid, 256>>>(
        (const float4*)x, w_embed, b_embed, gate_w, expert_w, expert_b,
        resid_w, resid_b, comb_w, comb_b, proj_w, proj_b,
        (float4*)d_out, (float*)d_out, n, out_size);
}

// round 4
// speedup vs baseline: 1.3463x; 1.0932x over previous
#include <cuda_runtime.h>

typedef unsigned long long ull;

// ---- packed f32x2 helpers (ptxas never auto-fuses these) ----
__device__ __forceinline__ ull fma2(ull a, ull b, ull c) {
    ull d; asm("fma.rn.f32x2 %0,%1,%2,%3;" : "=l"(d) : "l"(a), "l"(b), "l"(c)); return d;
}
__device__ __forceinline__ ull pk2(float lo, float hi) {
    ull d; asm("mov.b64 %0,{%1,%2};" : "=l"(d) : "f"(lo), "f"(hi)); return d;
}
__device__ __forceinline__ float2 upk2(ull v) {
    float2 r; asm("mov.b64 {%0,%1},%2;" : "=f"(r.x), "=f"(r.y) : "l"(v)); return r;
}
__device__ __forceinline__ float ex2(float x) {
    float r; asm("ex2.approx.ftz.f32 %0,%1;" : "=f"(r) : "f"(x)); return r;
}

#define LOG2E 1.4426950408889634f

// ---- folded params in d_P (floats) ----
// [0..32)   gate weights [i*8+e]  (log2e-prescaled)
// [32..40)  gate bias    [e]      (log2e-prescaled)
// [40..200) expert e*20: EP[i*4+j] (4x4 thru proj), epb at +16..+20
// [200..216) RP resid 4x4 thru proj
// [216..220) rpb
// [220..224) dC differenced combine (log2e-prescaled)
// [224]      dcb
// [232..236) pb proj bias (8B-aligned slot)
__device__ float        d_P[240];
__device__ double       d_acc[16];   // [0..8) sum gate probs, [8..16) argmax counts
__device__ unsigned int d_count;

// ================= setup: single-phase direct folds, no syncs =================
__global__ __launch_bounds__(256) void setup_kernel(
    const float* __restrict__ w_embed,  const float* __restrict__ b_embed,
    const float* __restrict__ gate_w,   const float* __restrict__ expert_w,
    const float* __restrict__ expert_b, const float* __restrict__ resid_w,
    const float* __restrict__ resid_b,  const float* __restrict__ comb_w,
    const float* __restrict__ comb_b,   const float* __restrict__ proj_w,
    const float* __restrict__ proj_b)
{
    const int t = threadIdx.x;

    if (t < 128) {                              // EP[e][i][j] = (w_embed@expert_w[e]@proj_w)
        int e = t >> 4, i = (t >> 2) & 3, j = t & 3;
        float acc = 0.f;
        #pragma unroll
        for (int k = 0; k < 16; k++) {
            float tmp = 0.f;
            #pragma unroll
            for (int m = 0; m < 16; m++)
                tmp = fmaf(w_embed[i * 16 + m], expert_w[(e * 16 + m) * 16 + k], tmp);
            acc = fmaf(tmp, proj_w[k * 4 + j], acc);
        }
        d_P[40 + e * 20 + i * 4 + j] = acc;
    } else if (t < 160) {                       // epb[e][j]
        int u = t - 128, e = u >> 2, j = u & 3;
        float acc = 0.f;
        #pragma unroll
        for (int k = 0; k < 16; k++) {
            float tmp = expert_b[e * 16 + k];
            #pragma unroll
            for (int m = 0; m < 16; m++)
                tmp = fmaf(b_embed[m], expert_w[(e * 16 + m) * 16 + k], tmp);
            acc = fmaf(tmp, proj_w[k * 4 + j], acc);
        }
        d_P[40 + e * 20 + 16 + j] = acc;
    } else if (t < 176) {                       // RP[i][j]
        int u = t - 160, i = u >> 2, j = u & 3;
        float acc = 0.f;
        #pragma unroll
        for (int k = 0; k < 16; k++) {
            float tmp = 0.f;
            #pragma unroll
            for (int m = 0; m < 16; m++)
                tmp = fmaf(w_embed[i * 16 + m], resid_w[m * 16 + k], tmp);
            acc = fmaf(tmp, proj_w[k * 4 + j], acc);
        }
        d_P[200 + i * 4 + j] = acc;
    } else if (t < 180) {                       // rpb[j]
        int j = t - 176;
        float acc = 0.f;
        #pragma unroll
        for (int k = 0; k < 16; k++) {
            float tmp = resid_b[k];
            #pragma unroll
            for (int m = 0; m < 16; m++)
                tmp = fmaf(b_embed[m], resid_w[m * 16 + k], tmp);
            acc = fmaf(tmp, proj_w[k * 4 + j], acc);
        }
        d_P[216 + j] = acc;
    } else if (t < 212) {                       // gate weights (log2e)
        int u = t - 180, i = u >> 3, e = u & 7;
        float acc = 0.f;
        #pragma unroll
        for (int m = 0; m < 16; m++)
            acc = fmaf(w_embed[i * 16 + m], gate_w[m * 8 + e], acc);
        d_P[i * 8 + e] = acc * LOG2E;
    } else if (t < 220) {                       // gate bias (log2e)
        int e = t - 212;
        float acc = 0.f;
        #pragma unroll
        for (int m = 0; m < 16; m++)
            acc = fmaf(b_embed[m], gate_w[m * 8 + e], acc);
        d_P[32 + e] = acc * LOG2E;
    } else if (t < 224) {                       // dC (log2e)
        int i = t - 220;
        float acc = 0.f;
        #pragma unroll
        for (int m = 0; m < 16; m++)
            acc = fmaf(w_embed[i * 16 + m], comb_w[m * 2 + 1] - comb_w[m * 2], acc);
        d_P[220 + i] = acc * LOG2E;
    } else if (t == 224) {                      // dcb (log2e)
        float acc = comb_b[1] - comb_b[0];
        #pragma unroll
        for (int m = 0; m < 16; m++)
            acc = fmaf(b_embed[m], comb_w[m * 2 + 1] - comb_w[m * 2], acc);
        d_P[224] = acc * LOG2E;
    } else if (t < 229) {                       // pb
        d_P[232 + (t - 225)] = proj_b[t - 225];
    } else if (t < 245) {                       // zero accumulators (replay-safe)
        d_acc[t - 229] = 0.0;
    } else if (t == 245) {
        d_count = 0u;
    }
}

// ================= main streaming kernel =================
__global__ __launch_bounds__(256) void moe_main_kernel(
    const float4* __restrict__ x4, float4* __restrict__ o4,
    float* __restrict__ out, int n, int out_size)
{
    __shared__ alignas(16) float P[240];
    __shared__ float red[8][16];
    __shared__ unsigned s_last;

    const int t = threadIdx.x;
    if (t < 240) P[t] = d_P[t];
    __syncthreads();

    // pair views (compiler hoists what it wants — no register forcing)
    const ull* Gp  = (const ull*)P;              // [i*4+k] rows, [16+k] bias
    const ull* Rp  = (const ull*)(P + 200);      // rows [i*2],[i*2+1]; bias [8],[9]
    const ull Pbp0 = ((const ull*)(P + 232))[0];
    const ull Pbp1 = ((const ull*)(P + 232))[1];
    const float Dc0 = P[220], Dc1 = P[221], Dc2 = P[222], Dc3 = P[223], Dcb = P[224];

    float S[8] = {0.f, 0.f, 0.f, 0.f, 0.f, 0.f, 0.f, 0.f};
    unsigned cnt = 0;        // 8 nibble counters (tokens/thread <= 15)

    const int stride = blockDim.x * gridDim.x;
    #pragma unroll 2
    for (int i = blockIdx.x * blockDim.x + t; i < n; i += stride) {
        const float4 xv = x4[i];
        const ull xx = pk2(xv.x, xv.x), yy = pk2(xv.y, xv.y);
        const ull zz = pk2(xv.z, xv.z), ww = pk2(xv.w, xv.w);

        // gate logits in log2 domain (4 packed pairs)
        float lg[8];
        #pragma unroll
        for (int k = 0; k < 4; k++) {
            ull v = fma2(xx, Gp[k],      Gp[16 + k]);
            v     = fma2(yy, Gp[4 + k],  v);
            v     = fma2(zz, Gp[8 + k],  v);
            v     = fma2(ww, Gp[12 + k], v);
            float2 f = upk2(v); lg[2 * k] = f.x; lg[2 * k + 1] = f.y;
        }

        // first-max argmax (matches jnp.argmax; positive scale preserves order)
        float m = lg[0]; int idx = 0;
        #pragma unroll
        for (int e = 1; e < 8; e++)
            if (lg[e] > m) { m = lg[e]; idx = e; }

        // softmax probs via ex2 (coeffs pre-scaled by log2e)
        float p[8], sum = 0.f;
        #pragma unroll
        for (int e = 0; e < 8; e++) { p[e] = ex2(lg[e] - m); sum += p[e]; }
        const float inv = __fdividef(1.f, sum);   // == gates[idx]
        #pragma unroll
        for (int e = 0; e < 8; e++) S[e] = fmaf(p[e], inv, S[e]);
        cnt += 1u << (idx << 2);

        // 2-way combine softmax == sigmoid of differenced linear form (log2 domain)
        const float dl = fmaf(xv.w, Dc3, fmaf(xv.z, Dc2,
                         fmaf(xv.y, Dc1, fmaf(xv.x, Dc0, Dcb))));
        const float cw0 = __fdividef(1.f, 1.f + ex2(dl));
        const float cw1 = 1.f - cw0;
        const float a   = cw0 * inv;

        // expert block: 5x LDS.128 (16B-aligned, 80B stride), packed math
        const ulonglong2* Ep = (const ulonglong2*)(P + 40 + idx * 20);
        const ulonglong2 e0 = Ep[0], e1 = Ep[1], e2 = Ep[2], e3 = Ep[3], e4 = Ep[4];
        ull v01 = fma2(xx, e0.x, e4.x);
        v01 = fma2(yy, e1.x, v01); v01 = fma2(zz, e2.x, v01); v01 = fma2(ww, e3.x, v01);
        ull v23 = fma2(xx, e0.y, e4.y);
        v23 = fma2(yy, e1.y, v23); v23 = fma2(zz, e2.y, v23); v23 = fma2(ww, e3.y, v23);

        // residual (pre-folded thru proj), packed
        ull r01 = fma2(xx, Rp[0], Rp[8]);
        r01 = fma2(yy, Rp[2], r01); r01 = fma2(zz, Rp[4], r01); r01 = fma2(ww, Rp[6], r01);
        ull r23 = fma2(xx, Rp[1], Rp[9]);
        r23 = fma2(yy, Rp[3], r23); r23 = fma2(zz, Rp[5], r23); r23 = fma2(ww, Rp[7], r23);

        const ull aa = pk2(a, a), cc = pk2(cw1, cw1);
        union { ull u[2]; float4 v; } ou;
        ou.u[0] = fma2(aa, v01, fma2(cc, r01, Pbp0));
        ou.u[1] = fma2(aa, v23, fma2(cc, r23, Pbp1));
        o4[i] = ou.v;
    }

    // ---- aux reduction: warp -> block -> global ----
    float Cf[8];
    #pragma unroll
    for (int e = 0; e < 8; e++) Cf[e] = (float)((cnt >> (e << 2)) & 0xFu);

    #pragma unroll
    for (int e = 0; e < 8; e++) {
        #pragma unroll
        for (int off = 16; off; off >>= 1) {
            S[e]  += __shfl_down_sync(0xffffffffu, S[e],  off);
            Cf[e] += __shfl_down_sync(0xffffffffu, Cf[e], off);
        }
    }
    const int lane = t & 31, w = t >> 5;
    if (lane == 0) {
        #pragma unroll
        for (int e = 0; e < 8; e++) { red[w][e] = S[e]; red[w][8 + e] = Cf[e]; }
    }
    __syncthreads();
    if (t < 16) {
        float v = 0.f;
        #pragma unroll
        for (int w2 = 0; w2 < 8; w2++) v += red[w2][t];
        atomicAdd(&d_acc[t], (double)v);
        __threadfence();
    }
    __syncthreads();

    // ---- last-block finalize (graph-replay-safe reset) ----
    if (t == 0) {
        unsigned old = atomicAdd(&d_count, 1u);
        s_last = (old == gridDim.x - 1) ? 1u : 0u;
    }
    __syncthreads();
    if (s_last && t == 0) {
        volatile double* acc = d_acc;
        double s = 0.0;
        #pragma unroll
        for (int e = 0; e < 8; e++) s += acc[e] * acc[8 + e];
        if (out_size > n * 4) {
            const double dn = (double)n;
            out[n * 4] = (float)(8.0 * s / (dn * dn));
        }
        #pragma unroll
        for (int k = 0; k < 16; k++) acc[k] = 0.0;
        __threadfence();
        d_count = 0u;
    }
}

extern "C" void kernel_launch(void* const* d_in, const int* in_sizes, int n_in,
                              void* d_out, int out_size)
{
    const float* x        = (const float*)d_in[0];
    const float* w_embed  = (const float*)d_in[1];
    const float* b_embed  = (const float*)d_in[2];
    const float* gate_w   = (const float*)d_in[3];
    const float* expert_w = (const float*)d_in[4];
    const float* expert_b = (const float*)d_in[5];
    const float* resid_w  = (const float*)d_in[6];
    const float* resid_b  = (const float*)d_in[7];
    const float* comb_w   = (const float*)d_in[8];
    const float* comb_b   = (const float*)d_in[9];
    const float* proj_w   = (const float*)d_in[10];
    const float* proj_b   = (const float*)d_in[11];

    const int n = in_sizes[0] / 4;          // tokens

    setup_kernel<<<1, 256>>>(w_embed, b_embed, gate_w, expert_w, expert_b,
                             resid_w, resid_b, comb_w, comb_b, proj_w, proj_b);

    // R1-proven shape: 8 tokens/thread at n=1M; nibble-safe (<=15) in general
    int grid = (n + 256 * 8 - 1) / (256 * 8);
    int min_grid = (n + 256 * 15 - 1) / (256 * 15);
    if (grid < min_grid) grid = min_grid;
    if (grid < 1) grid = 1;

    moe_main_kernel<<<grid, 256>>>((const float4*)x, (float4*)d_out,
                                   (float*)d_out, n, out_size);
}